// round 10
// baseline (speedup 1.0000x reference)
#include <cuda_runtime.h>
#include <math.h>
#include <stdint.h>

// Problem constants
#define N_W   80000
#define N_D   16000
#define E_WW  200000
#define E_WD  200000
#define HF    512      // H*F = 4*128
#define F_OUT 128
#define H_N   4

// GEMM tiling
#define BM 128
#define BN 128
#define BK 16
#define AS_STRIDE 28    // floats; conflict-free frag reads, rows 16B-multiple
#define BS_STRIDE 136   // floats; >=128 cols + pad -> conflict-free, 16B-multiple

// ---------------------------------------------------------------------------
// Static device scratch (allocation-free rule)
// ---------------------------------------------------------------------------
__device__ float g_z_ww[(size_t)N_W * HF];
__device__ float g_z_wd[(size_t)N_W * HF];
__device__ float g_zd_wd[(size_t)N_D * HF];
__device__ float g_el_ww[N_W * H_N];
__device__ float g_er_ww[N_W * H_N];
__device__ float g_el_wd[N_W * H_N];
__device__ float g_er_wd[N_D * H_N];
__device__ float g_xw1[(size_t)N_W * F_OUT];
__device__ float g_xd1[(size_t)N_D * F_OUT];
__device__ float g_xw_r[(size_t)N_W * 256];   // tf32-rounded x_word
__device__ float g_xd_r[(size_t)N_D * 256];   // tf32-rounded x_doc
__device__ float g_w0a[256 * 512];            // tf32-rounded W_ww0
__device__ float g_w0b[256 * 512];            // tf32-rounded W_wd0
__device__ float g_w1a[128 * 512];            // tf32-rounded W_ww1
__device__ float g_w1b[128 * 512];            // tf32-rounded W_wd1
__device__ int   g_deg_ww[N_W];
__device__ int   g_deg_wd[N_D];
__device__ int   g_beg_ww[N_W];
__device__ int   g_beg_wd[N_D];
__device__ int   g_cur[N_W];
__device__ int   g_ci_ww[E_WW];
__device__ int   g_ci_wd[E_WD];
__device__ int   g_total[2];

// ---------------------------------------------------------------------------
// helpers
// ---------------------------------------------------------------------------
__device__ __forceinline__ uint32_t f2tf(float x) {
    uint32_t r;
    asm("cvt.rna.tf32.f32 %0, %1;" : "=r"(r) : "f"(x));
    return r;
}
__device__ __forceinline__ float roundtf(float x) {
    return __uint_as_float(f2tf(x));
}
__device__ __forceinline__ void cpa16(uint32_t dst, const float* src) {
    asm volatile("cp.async.cg.shared.global [%0], [%1], 16;" :: "r"(dst), "l"(src));
}
__device__ __forceinline__ void cp_commit() {
    asm volatile("cp.async.commit_group;");
}
__device__ __forceinline__ void mma_tf32(float* d, const uint32_t* a, const uint32_t* b) {
    asm volatile(
        "mma.sync.aligned.m16n8k8.row.col.f32.tf32.tf32.f32 "
        "{%0,%1,%2,%3}, {%4,%5,%6,%7}, {%8,%9}, {%0,%1,%2,%3};\n"
        : "+f"(d[0]), "+f"(d[1]), "+f"(d[2]), "+f"(d[3])
        : "r"(a[0]), "r"(a[1]), "r"(a[2]), "r"(a[3]), "r"(b[0]), "r"(b[1]));
}

// ---------------------------------------------------------------------------
// tf32 pre-rounding kernels
// ---------------------------------------------------------------------------
__global__ void k_round(const float4* __restrict__ src, float4* __restrict__ dst, int n4) {
    int i = blockIdx.x * blockDim.x + threadIdx.x;
    if (i < n4) {
        float4 v = src[i];
        v.x = roundtf(v.x); v.y = roundtf(v.y);
        v.z = roundtf(v.z); v.w = roundtf(v.w);
        dst[i] = v;
    }
}

// round 4 arrays in one launch (keeps launch indices stable for profiling)
__global__ void k_round4(const float4* s0, float4* d0, int n0,
                         const float4* s1, float4* d1, int n1,
                         const float4* s2, float4* d2, int n2,
                         const float4* s3, float4* d3, int n3) {
    int i = blockIdx.x * blockDim.x + threadIdx.x;
    const float4* s; float4* d; int j = i;
    if (j < n0) { s = s0; d = d0; }
    else { j -= n0;
        if (j < n1) { s = s1; d = d1; }
        else { j -= n1;
            if (j < n2) { s = s2; d = d2; }
            else { j -= n2;
                if (j < n3) { s = s3; d = d3; }
                else return;
            }
        }
    }
    float4 v = s[j];
    v.x = roundtf(v.x); v.y = roundtf(v.y);
    v.z = roundtf(v.z); v.w = roundtf(v.w);
    d[j] = v;
}

// ---------------------------------------------------------------------------
// CSR build (unordered contiguous segments — no serial scan needed)
// ---------------------------------------------------------------------------
__global__ void k_zero_int(int* p, int n) {
    int i = blockIdx.x * blockDim.x + threadIdx.x;
    if (i < n) p[i] = 0;
}

__global__ void k_hist(const int* __restrict__ dst, int n, int* __restrict__ deg) {
    int i = blockIdx.x * blockDim.x + threadIdx.x;
    if (i < n) atomicAdd(&deg[dst[i]], 1);
}

__global__ void k_offsets(const int* __restrict__ deg, int* __restrict__ beg,
                          int* __restrict__ total, int n) {
    int i = blockIdx.x * blockDim.x + threadIdx.x;
    int lane = threadIdx.x & 31;
    int v = (i < n) ? deg[i] : 0;
    int s = v;
    #pragma unroll
    for (int off = 1; off < 32; off <<= 1) {
        int t = __shfl_up_sync(0xffffffffu, s, off);
        if (lane >= off) s += t;
    }
    int wtot = __shfl_sync(0xffffffffu, s, 31);
    int base = 0;
    if (lane == 31) base = atomicAdd(total, wtot);
    base = __shfl_sync(0xffffffffu, base, 31);
    if (i < n) beg[i] = base + s - v;
}

__global__ void k_scatter(const int* __restrict__ src, const int* __restrict__ dst,
                          int n, const int* __restrict__ beg,
                          int* __restrict__ cur, int* __restrict__ ci) {
    int i = blockIdx.x * blockDim.x + threadIdx.x;
    if (i < n) {
        int d = dst[i];
        int p = atomicAdd(&cur[d], 1);
        ci[beg[d] + p] = src[i];
    }
}

// ---------------------------------------------------------------------------
// TF32 tensor-core GEMM: C[M,512] = A[M,K] @ B[K,512]
// Inputs must be PRE-ROUNDED to tf32 values (raw bits fed to mma).
// 128x128 tile, 8 warps (2m x 4n), mma.m16n8k8.tf32, cp.async double-buffered.
// Fused per-head attention-dot epilogue.
// ---------------------------------------------------------------------------
__global__ __launch_bounds__(256, 2) void k_gemm_tc(
    const float* __restrict__ A, const float* __restrict__ B,
    float* __restrict__ C,
    const float* __restrict__ v1, const float* __restrict__ v2,
    float* __restrict__ o1, float* __restrict__ o2,
    int M, int K) {
    __shared__ __align__(16) float As[2][BM][AS_STRIDE];
    __shared__ __align__(16) float Bs[2][BK][BS_STRIDE];
    __shared__ float sdot1[BM];
    __shared__ float sdot2[BM];

    int tid = threadIdx.x;
    int lane = tid & 31, wid = tid >> 5;
    int g = lane >> 2, t4 = lane & 3;
    int wm = wid & 1, wn = wid >> 1;
    int bm = blockIdx.y * BM;
    int h  = blockIdx.x;
    int bn = h * BN;

    if (tid < BM) { sdot1[tid] = 0.f; sdot2[tid] = 0.f; }

    int a_row = tid >> 2;            // 0..63 (also +64)
    int a_kq  = (tid & 3) * 4;       // 0,4,8,12
    int b_row = tid >> 5;            // 0..7 (also +8)
    int b_nc  = (tid & 31) * 4;      // 0..124

    const float* Ap = A + (size_t)bm * K;

    uint32_t as_base = (uint32_t)__cvta_generic_to_shared(&As[0][0][0]);
    uint32_t bs_base = (uint32_t)__cvta_generic_to_shared(&Bs[0][0][0]);
    const uint32_t AS_BUF = BM * AS_STRIDE * 4;
    const uint32_t BS_BUF = BK * BS_STRIDE * 4;

    float acc[4][4][4] = {};

    int nk = K / BK;

    {
        cpa16(as_base + (a_row * AS_STRIDE + a_kq) * 4, Ap + (size_t)a_row * K + a_kq);
        cpa16(as_base + ((a_row + 64) * AS_STRIDE + a_kq) * 4, Ap + (size_t)(a_row + 64) * K + a_kq);
        cpa16(bs_base + (b_row * BS_STRIDE + b_nc) * 4, B + (size_t)b_row * 512 + bn + b_nc);
        cpa16(bs_base + ((b_row + 8) * BS_STRIDE + b_nc) * 4, B + (size_t)(b_row + 8) * 512 + bn + b_nc);
        cp_commit();
    }

    for (int kt = 0; kt < nk; kt++) {
        int cur = kt & 1;
        bool more = (kt + 1 < nk);
        if (more) {
            int nxt = cur ^ 1;
            int k0 = (kt + 1) * BK;
            uint32_t ab = as_base + nxt * AS_BUF;
            uint32_t bb = bs_base + nxt * BS_BUF;
            cpa16(ab + (a_row * AS_STRIDE + a_kq) * 4, Ap + (size_t)a_row * K + k0 + a_kq);
            cpa16(ab + ((a_row + 64) * AS_STRIDE + a_kq) * 4, Ap + (size_t)(a_row + 64) * K + k0 + a_kq);
            cpa16(bb + (b_row * BS_STRIDE + b_nc) * 4, B + (size_t)(k0 + b_row) * 512 + bn + b_nc);
            cpa16(bb + ((b_row + 8) * BS_STRIDE + b_nc) * 4, B + (size_t)(k0 + b_row + 8) * 512 + bn + b_nc);
            cp_commit();
            asm volatile("cp.async.wait_group 1;");
        } else {
            asm volatile("cp.async.wait_group 0;");
        }
        __syncthreads();

        #pragma unroll
        for (int s = 0; s < 2; s++) {
            uint32_t a[4][4], b[4][2];
            #pragma unroll
            for (int mi = 0; mi < 4; mi++) {
                int r = wm * 64 + mi * 16;
                a[mi][0] = __float_as_uint(As[cur][r + g][s * 8 + t4]);
                a[mi][1] = __float_as_uint(As[cur][r + 8 + g][s * 8 + t4]);
                a[mi][2] = __float_as_uint(As[cur][r + g][s * 8 + t4 + 4]);
                a[mi][3] = __float_as_uint(As[cur][r + 8 + g][s * 8 + t4 + 4]);
            }
            #pragma unroll
            for (int nj = 0; nj < 4; nj++) {
                int c = wn * 32 + nj * 8 + g;
                b[nj][0] = __float_as_uint(Bs[cur][s * 8 + t4][c]);
                b[nj][1] = __float_as_uint(Bs[cur][s * 8 + t4 + 4][c]);
            }
            #pragma unroll
            for (int mi = 0; mi < 4; mi++)
                #pragma unroll
                for (int nj = 0; nj < 4; nj++)
                    mma_tf32(acc[mi][nj], a[mi], b[nj]);
        }
        __syncthreads();
    }

    #pragma unroll
    for (int mi = 0; mi < 4; mi++) {
        int r0 = bm + wm * 64 + mi * 16 + g;
        int r1 = r0 + 8;
        #pragma unroll
        for (int nj = 0; nj < 4; nj++) {
            int c = bn + wn * 32 + nj * 8 + 2 * t4;
            *(float2*)(C + (size_t)r0 * 512 + c) = make_float2(acc[mi][nj][0], acc[mi][nj][1]);
            *(float2*)(C + (size_t)r1 * 512 + c) = make_float2(acc[mi][nj][2], acc[mi][nj][3]);
        }
    }

    if (o1 || o2) {
        float w1v[4][2], w2v[4][2];
        #pragma unroll
        for (int nj = 0; nj < 4; nj++) {
            int c = wn * 32 + nj * 8 + 2 * t4;
            if (o1) { w1v[nj][0] = v1[h * 128 + c]; w1v[nj][1] = v1[h * 128 + c + 1]; }
            if (o2) { w2v[nj][0] = v2[h * 128 + c]; w2v[nj][1] = v2[h * 128 + c + 1]; }
        }
        #pragma unroll
        for (int mi = 0; mi < 4; mi++) {
            float p0 = 0.f, p1 = 0.f, q0 = 0.f, q1 = 0.f;
            #pragma unroll
            for (int nj = 0; nj < 4; nj++) {
                if (o1) {
                    p0 += acc[mi][nj][0] * w1v[nj][0] + acc[mi][nj][1] * w1v[nj][1];
                    p1 += acc[mi][nj][2] * w1v[nj][0] + acc[mi][nj][3] * w1v[nj][1];
                }
                if (o2) {
                    q0 += acc[mi][nj][0] * w2v[nj][0] + acc[mi][nj][1] * w2v[nj][1];
                    q1 += acc[mi][nj][2] * w2v[nj][0] + acc[mi][nj][3] * w2v[nj][1];
                }
            }
            p0 += __shfl_down_sync(0xffffffffu, p0, 2, 4);
            p0 += __shfl_down_sync(0xffffffffu, p0, 1, 4);
            p1 += __shfl_down_sync(0xffffffffu, p1, 2, 4);
            p1 += __shfl_down_sync(0xffffffffu, p1, 1, 4);
            q0 += __shfl_down_sync(0xffffffffu, q0, 2, 4);
            q0 += __shfl_down_sync(0xffffffffu, q0, 1, 4);
            q1 += __shfl_down_sync(0xffffffffu, q1, 2, 4);
            q1 += __shfl_down_sync(0xffffffffu, q1, 1, 4);
            if (t4 == 0) {
                int lr = wm * 64 + mi * 16 + g;
                if (o1) { atomicAdd(&sdot1[lr], p0); atomicAdd(&sdot1[lr + 8], p1); }
                if (o2) { atomicAdd(&sdot2[lr], q0); atomicAdd(&sdot2[lr + 8], q1); }
            }
        }
        __syncthreads();
        if (tid < BM) {
            if (o1) o1[(bm + tid) * H_N + h] = sdot1[tid];
            if (o2) o2[(bm + tid) * H_N + h] = sdot2[tid];
        }
    }
}

// ---------------------------------------------------------------------------
// Fused aggregation: per dst node, two-pass softmax over incoming edges,
// weighted sum of zs[src], + bias, head-sum, relu. 128 threads = 4 heads.
// round_out=1 rounds the output to tf32 values (feeds next-layer GEMM).
// ---------------------------------------------------------------------------
__global__ __launch_bounds__(128) void k_aggregate(
    const int* __restrict__ begp, const int* __restrict__ degp,
    const int* __restrict__ ci,
    const float* __restrict__ z,
    const float* __restrict__ el, const float* __restrict__ er,
    const float* __restrict__ bias,
    float* __restrict__ out, int n, int round_out) {
    int node = blockIdx.x;
    if (node >= n) return;
    int t = threadIdx.x;
    int h = t >> 5, lane = t & 31;
    int col = h * F_OUT + lane * 4;

    int beg = begp[node];
    int end = beg + degp[node];
    float erh = er[node * H_N + h];

    float m = -3.0e38f;
    for (int j = beg; j < end; j++) {
        int s = ci[j];
        float e = el[s * H_N + h] + erh;
        e = (e > 0.f) ? e : 0.2f * e;
        m = fmaxf(m, e);
    }

    float4 acc = make_float4(0.f, 0.f, 0.f, 0.f);
    float ssum = 0.f;
    for (int j = beg; j < end; j++) {
        int s = ci[j];
        float e = el[s * H_N + h] + erh;
        e = (e > 0.f) ? e : 0.2f * e;
        float w = __expf(e - m);
        float4 zv = *(const float4*)(z + (size_t)s * HF + col);
        acc.x += w * zv.x; acc.y += w * zv.y;
        acc.z += w * zv.z; acc.w += w * zv.w;
        ssum += w;
    }

    float4 bv = *(const float4*)(bias + col);
    float4 o;
    if (end > beg) {
        float inv = 1.f / ssum;
        o = make_float4(acc.x * inv + bv.x, acc.y * inv + bv.y,
                        acc.z * inv + bv.z, acc.w * inv + bv.w);
    } else {
        o = bv;
    }

    __shared__ float sm[HF];
    *(float4*)(&sm[col]) = o;
    __syncthreads();
    float r = sm[t] + sm[128 + t] + sm[256 + t] + sm[384 + t];
    r = fmaxf(r, 0.f);
    if (round_out) r = roundtf(r);
    out[(size_t)node * F_OUT + t] = r;
}

// ---------------------------------------------------------------------------
// Host launch
// ---------------------------------------------------------------------------
extern "C" void kernel_launch(void* const* d_in, const int* in_sizes, int n_in,
                              void* d_out, int out_size) {
    const float* x_word = (const float*)d_in[0];
    const float* x_doc  = (const float*)d_in[1];
    const float* W_ww0  = (const float*)d_in[2];
    const float* al_ww0 = (const float*)d_in[3];
    const float* ar_ww0 = (const float*)d_in[4];
    const float* b_ww0  = (const float*)d_in[5];
    const float* W_wd0  = (const float*)d_in[6];
    const float* al_wd0 = (const float*)d_in[7];
    const float* ar_wd0 = (const float*)d_in[8];
    const float* b_wd0  = (const float*)d_in[9];
    const float* W_ww1  = (const float*)d_in[10];
    const float* al_ww1 = (const float*)d_in[11];
    const float* ar_ww1 = (const float*)d_in[12];
    const float* b_ww1  = (const float*)d_in[13];
    const float* W_wd1  = (const float*)d_in[14];
    const float* al_wd1 = (const float*)d_in[15];
    const float* ar_wd1 = (const float*)d_in[16];
    const float* b_wd1  = (const float*)d_in[17];
    const int* ww_src = (const int*)d_in[18];
    const int* ww_dst = (const int*)d_in[19];
    const int* wd_src = (const int*)d_in[20];
    const int* wd_dst = (const int*)d_in[21];

    float* out = (float*)d_out;

    float *z_ww, *z_wd, *zd_wd, *el_ww, *er_ww, *el_wd, *er_wd, *xw1, *xd1;
    float *xw_r, *xd_r, *w0a, *w0b, *w1a, *w1b;
    int *deg_ww, *deg_wd, *beg_ww, *beg_wd, *cur, *ci_ww, *ci_wd, *total;
    cudaGetSymbolAddress((void**)&z_ww, g_z_ww);
    cudaGetSymbolAddress((void**)&z_wd, g_z_wd);
    cudaGetSymbolAddress((void**)&zd_wd, g_zd_wd);
    cudaGetSymbolAddress((void**)&el_ww, g_el_ww);
    cudaGetSymbolAddress((void**)&er_ww, g_er_ww);
    cudaGetSymbolAddress((void**)&el_wd, g_el_wd);
    cudaGetSymbolAddress((void**)&er_wd, g_er_wd);
    cudaGetSymbolAddress((void**)&xw1, g_xw1);
    cudaGetSymbolAddress((void**)&xd1, g_xd1);
    cudaGetSymbolAddress((void**)&xw_r, g_xw_r);
    cudaGetSymbolAddress((void**)&xd_r, g_xd_r);
    cudaGetSymbolAddress((void**)&w0a, g_w0a);
    cudaGetSymbolAddress((void**)&w0b, g_w0b);
    cudaGetSymbolAddress((void**)&w1a, g_w1a);
    cudaGetSymbolAddress((void**)&w1b, g_w1b);
    cudaGetSymbolAddress((void**)&deg_ww, g_deg_ww);
    cudaGetSymbolAddress((void**)&deg_wd, g_deg_wd);
    cudaGetSymbolAddress((void**)&beg_ww, g_beg_ww);
    cudaGetSymbolAddress((void**)&beg_wd, g_beg_wd);
    cudaGetSymbolAddress((void**)&cur, g_cur);
    cudaGetSymbolAddress((void**)&ci_ww, g_ci_ww);
    cudaGetSymbolAddress((void**)&ci_wd, g_ci_wd);
    cudaGetSymbolAddress((void**)&total, g_total);

    const int TB = 256;

    // ---- 0,1: round x inputs; 2: round all 4 W mats ----
    {
        int n4w = N_W * 256 / 4;
        k_round<<<(n4w + TB - 1) / TB, TB>>>((const float4*)x_word, (float4*)xw_r, n4w);
        int n4d = N_D * 256 / 4;
        k_round<<<(n4d + TB - 1) / TB, TB>>>((const float4*)x_doc, (float4*)xd_r, n4d);
        int a = 256 * 512 / 4, bsz = 128 * 512 / 4;
        int tot = a + a + bsz + bsz;
        k_round4<<<(tot + TB - 1) / TB, TB>>>(
            (const float4*)W_ww0, (float4*)w0a, a,
            (const float4*)W_wd0, (float4*)w0b, a,
            (const float4*)W_ww1, (float4*)w1a, bsz,
            (const float4*)W_wd1, (float4*)w1b, bsz);
    }

    // ---- 3: big ww0 GEMM (profiled launch index 3) ----
    k_gemm_tc<<<dim3(4, N_W / BM), 256>>>(xw_r, w0a, z_ww, al_ww0, ar_ww0,
                                          el_ww, er_ww, N_W, 256);
    k_gemm_tc<<<dim3(4, N_W / BM), 256>>>(xw_r, w0b, z_wd, al_wd0, nullptr,
                                          el_wd, nullptr, N_W, 256);
    k_gemm_tc<<<dim3(4, N_D / BM), 256>>>(xd_r, w0b, zd_wd, nullptr, ar_wd0,
                                          nullptr, er_wd, N_D, 256);

    // ---- CSR ww ----
    k_zero_int<<<(N_W + TB - 1) / TB, TB>>>(deg_ww, N_W);
    k_zero_int<<<1, 32>>>(total, 2);
    k_hist<<<(E_WW + TB - 1) / TB, TB>>>(ww_dst, E_WW, deg_ww);
    k_offsets<<<(N_W + TB - 1) / TB, TB>>>(deg_ww, beg_ww, total, N_W);
    k_zero_int<<<(N_W + TB - 1) / TB, TB>>>(cur, N_W);
    k_scatter<<<(E_WW + TB - 1) / TB, TB>>>(ww_src, ww_dst, E_WW, beg_ww, cur, ci_ww);
    // ---- CSR wd ----
    k_zero_int<<<(N_D + TB - 1) / TB, TB>>>(deg_wd, N_D);
    k_hist<<<(E_WD + TB - 1) / TB, TB>>>(wd_dst, E_WD, deg_wd);
    k_offsets<<<(N_D + TB - 1) / TB, TB>>>(deg_wd, beg_wd, total + 1, N_D);
    k_zero_int<<<(N_D + TB - 1) / TB, TB>>>(cur, N_D);
    k_scatter<<<(E_WD + TB - 1) / TB, TB>>>(wd_src, wd_dst, E_WD, beg_wd, cur, ci_wd);

    // ---- Layer 0 aggregation (outputs rounded to tf32 for next GEMM) ----
    k_aggregate<<<N_W, 128>>>(beg_ww, deg_ww, ci_ww, z_ww, el_ww, er_ww, b_ww0, xw1, N_W, 1);
    k_aggregate<<<N_D, 128>>>(beg_wd, deg_wd, ci_wd, z_wd, el_wd, er_wd, b_wd0, xd1, N_D, 1);

    // ---- Layer 1 ----
    k_gemm_tc<<<dim3(4, N_W / BM), 256>>>(xw1, w1a, z_ww, al_ww1, ar_ww1,
                                          el_ww, er_ww, N_W, 128);
    k_gemm_tc<<<dim3(4, N_W / BM), 256>>>(xw1, w1b, z_wd, al_wd1, nullptr,
                                          el_wd, nullptr, N_W, 128);
    k_gemm_tc<<<dim3(4, N_D / BM), 256>>>(xd1, w1b, zd_wd, nullptr, ar_wd1,
                                          nullptr, er_wd, N_D, 128);
    k_aggregate<<<N_W, 128>>>(beg_ww, deg_ww, ci_ww, z_ww, el_ww, er_ww, b_ww1, out, N_W, 0);
    k_aggregate<<<N_D, 128>>>(beg_wd, deg_wd, ci_wd, z_wd, el_wd, er_wd, b_wd1,
                              out + (size_t)N_W * F_OUT, N_D, 0);
}

// round 12
// speedup vs baseline: 1.0076x; 1.0076x over previous
#include <cuda_runtime.h>
#include <math.h>
#include <stdint.h>

// Problem constants
#define N_W   80000
#define N_D   16000
#define E_WW  200000
#define E_WD  200000
#define HF    512      // H*F = 4*128
#define F_OUT 128
#define H_N   4

// GEMM tiling
#define BM 128
#define BN 128
#define BK 16
#define NSTAGE 4
#define AS_STRIDE 28    // floats; conflict-free frag reads, rows 16B-multiple
#define BS_STRIDE 136   // floats; >=128 cols + pad -> conflict-free, 16B-multiple
#define AS_TILE (BM * AS_STRIDE)           // floats per A stage
#define BS_TILE (BK * BS_STRIDE)           // floats per B stage
#define DYN_SMEM ((NSTAGE * (AS_TILE + BS_TILE)) * 4)   // bytes = 92160

// ---------------------------------------------------------------------------
// Static device scratch (allocation-free rule)
// ---------------------------------------------------------------------------
__device__ float g_z_ww[(size_t)N_W * HF];
__device__ float g_z_wd[(size_t)N_W * HF];
__device__ float g_zd_wd[(size_t)N_D * HF];
__device__ float g_el_ww[N_W * H_N];
__device__ float g_er_ww[N_W * H_N];
__device__ float g_el_wd[N_W * H_N];
__device__ float g_er_wd[N_D * H_N];
__device__ float g_xw1[(size_t)N_W * F_OUT];
__device__ float g_xd1[(size_t)N_D * F_OUT];
__device__ float g_xw_r[(size_t)N_W * 256];   // tf32-rounded x_word
__device__ float g_xd_r[(size_t)N_D * 256];   // tf32-rounded x_doc
__device__ float g_w0a[256 * 512];            // tf32-rounded W_ww0
__device__ float g_w0b[256 * 512];            // tf32-rounded W_wd0
__device__ float g_w1a[128 * 512];            // tf32-rounded W_ww1
__device__ float g_w1b[128 * 512];            // tf32-rounded W_wd1
__device__ int   g_deg_ww[N_W];
__device__ int   g_deg_wd[N_D];
__device__ int   g_beg_ww[N_W];
__device__ int   g_beg_wd[N_D];
__device__ int   g_cur[N_W];
__device__ int   g_ci_ww[E_WW];
__device__ int   g_ci_wd[E_WD];
__device__ int   g_total[2];

// ---------------------------------------------------------------------------
// helpers
// ---------------------------------------------------------------------------
__device__ __forceinline__ uint32_t f2tf(float x) {
    uint32_t r;
    asm("cvt.rna.tf32.f32 %0, %1;" : "=r"(r) : "f"(x));
    return r;
}
__device__ __forceinline__ float roundtf(float x) {
    return __uint_as_float(f2tf(x));
}
__device__ __forceinline__ void cpa16(uint32_t dst, const float* src) {
    asm volatile("cp.async.cg.shared.global [%0], [%1], 16;" :: "r"(dst), "l"(src));
}
__device__ __forceinline__ void cp_commit() {
    asm volatile("cp.async.commit_group;");
}
__device__ __forceinline__ void mma_tf32(float* d, const uint32_t* a, const uint32_t* b) {
    asm volatile(
        "mma.sync.aligned.m16n8k8.row.col.f32.tf32.tf32.f32 "
        "{%0,%1,%2,%3}, {%4,%5,%6,%7}, {%8,%9}, {%0,%1,%2,%3};\n"
        : "+f"(d[0]), "+f"(d[1]), "+f"(d[2]), "+f"(d[3])
        : "r"(a[0]), "r"(a[1]), "r"(a[2]), "r"(a[3]), "r"(b[0]), "r"(b[1]));
}

// ---------------------------------------------------------------------------
// tf32 pre-rounding kernels
// ---------------------------------------------------------------------------
__global__ void k_round(const float4* __restrict__ src, float4* __restrict__ dst, int n4) {
    int i = blockIdx.x * blockDim.x + threadIdx.x;
    if (i < n4) {
        float4 v = src[i];
        v.x = roundtf(v.x); v.y = roundtf(v.y);
        v.z = roundtf(v.z); v.w = roundtf(v.w);
        dst[i] = v;
    }
}

__global__ void k_round4(const float4* s0, float4* d0, int n0,
                         const float4* s1, float4* d1, int n1,
                         const float4* s2, float4* d2, int n2,
                         const float4* s3, float4* d3, int n3) {
    int i = blockIdx.x * blockDim.x + threadIdx.x;
    const float4* s; float4* d; int j = i;
    if (j < n0) { s = s0; d = d0; }
    else { j -= n0;
        if (j < n1) { s = s1; d = d1; }
        else { j -= n1;
            if (j < n2) { s = s2; d = d2; }
            else { j -= n2;
                if (j < n3) { s = s3; d = d3; }
                else return;
            }
        }
    }
    float4 v = s[j];
    v.x = roundtf(v.x); v.y = roundtf(v.y);
    v.z = roundtf(v.z); v.w = roundtf(v.w);
    d[j] = v;
}

// ---------------------------------------------------------------------------
// CSR build (unordered contiguous segments)
// ---------------------------------------------------------------------------
__global__ void k_zero_int(int* p, int n) {
    int i = blockIdx.x * blockDim.x + threadIdx.x;
    if (i < n) p[i] = 0;
}

__global__ void k_hist(const int* __restrict__ dst, int n, int* __restrict__ deg) {
    int i = blockIdx.x * blockDim.x + threadIdx.x;
    if (i < n) atomicAdd(&deg[dst[i]], 1);
}

__global__ void k_offsets(const int* __restrict__ deg, int* __restrict__ beg,
                          int* __restrict__ total, int n) {
    int i = blockIdx.x * blockDim.x + threadIdx.x;
    int lane = threadIdx.x & 31;
    int v = (i < n) ? deg[i] : 0;
    int s = v;
    #pragma unroll
    for (int off = 1; off < 32; off <<= 1) {
        int t = __shfl_up_sync(0xffffffffu, s, off);
        if (lane >= off) s += t;
    }
    int wtot = __shfl_sync(0xffffffffu, s, 31);
    int base = 0;
    if (lane == 31) base = atomicAdd(total, wtot);
    base = __shfl_sync(0xffffffffu, base, 31);
    if (i < n) beg[i] = base + s - v;
}

__global__ void k_scatter(const int* __restrict__ src, const int* __restrict__ dst,
                          int n, const int* __restrict__ beg,
                          int* __restrict__ cur, int* __restrict__ ci) {
    int i = blockIdx.x * blockDim.x + threadIdx.x;
    if (i < n) {
        int d = dst[i];
        int p = atomicAdd(&cur[d], 1);
        ci[beg[d] + p] = src[i];
    }
}

// ---------------------------------------------------------------------------
// TF32 tensor-core GEMM: C[M,512] = A[M,K] @ B[K,512]
// Inputs PRE-ROUNDED to tf32 values (raw bits fed to mma).
// 128x128 tile, 8 warps, mma.m16n8k8.tf32.
// 4-stage cp.async pipeline, ONE __syncthreads per BK iteration.
// Fused per-head attention-dot epilogue.
// ---------------------------------------------------------------------------
__global__ __launch_bounds__(256, 2) void k_gemm_tc(
    const float* __restrict__ A, const float* __restrict__ B,
    float* __restrict__ C,
    const float* __restrict__ v1, const float* __restrict__ v2,
    float* __restrict__ o1, float* __restrict__ o2,
    int M, int K) {
    extern __shared__ __align__(16) float dsm[];
    __shared__ float sdot1[BM];
    __shared__ float sdot2[BM];

    float* AsBase = dsm;                       // NSTAGE * AS_TILE
    float* BsBase = dsm + NSTAGE * AS_TILE;    // NSTAGE * BS_TILE

    int tid = threadIdx.x;
    int lane = tid & 31, wid = tid >> 5;
    int g = lane >> 2, t4 = lane & 3;
    int wm = wid & 1, wn = wid >> 1;
    int bm = blockIdx.y * BM;
    int h  = blockIdx.x;
    int bn = h * BN;

    if (tid < BM) { sdot1[tid] = 0.f; sdot2[tid] = 0.f; }

    int a_row = tid >> 2;            // 0..63 (also +64)
    int a_kq  = (tid & 3) * 4;       // 0,4,8,12
    int b_row = tid >> 5;            // 0..7 (also +8)
    int b_nc  = (tid & 31) * 4;      // 0..124

    const float* Ap = A + (size_t)bm * K;

    uint32_t as_base = (uint32_t)__cvta_generic_to_shared(AsBase);
    uint32_t bs_base = (uint32_t)__cvta_generic_to_shared(BsBase);
    const uint32_t AS_BUF = AS_TILE * 4;
    const uint32_t BS_BUF = BS_TILE * 4;

    float acc[4][4][4] = {};

    int nk = K / BK;

    // prologue: stage buffers 0..2
    #pragma unroll
    for (int st = 0; st < NSTAGE - 1; st++) {
        int k0 = st * BK;
        uint32_t ab = as_base + st * AS_BUF;
        uint32_t bb = bs_base + st * BS_BUF;
        cpa16(ab + (a_row * AS_STRIDE + a_kq) * 4, Ap + (size_t)a_row * K + k0 + a_kq);
        cpa16(ab + ((a_row + 64) * AS_STRIDE + a_kq) * 4, Ap + (size_t)(a_row + 64) * K + k0 + a_kq);
        cpa16(bb + (b_row * BS_STRIDE + b_nc) * 4, B + (size_t)(k0 + b_row) * 512 + bn + b_nc);
        cpa16(bb + ((b_row + 8) * BS_STRIDE + b_nc) * 4, B + (size_t)(k0 + b_row + 8) * 512 + bn + b_nc);
        cp_commit();
    }

    for (int kt = 0; kt < nk; kt++) {
        int st = kt & (NSTAGE - 1);
        // wait for stage kt (exactly NSTAGE-2 newer groups may remain in flight)
        asm volatile("cp.async.wait_group %0;" :: "n"(NSTAGE - 2));
        __syncthreads();   // data visibility + protects buffer reuse below

        // issue stage kt+3 (into the buffer computed at iter kt-1; safe after barrier)
        if (kt + NSTAGE - 1 < nk) {
            int kf = kt + NSTAGE - 1;
            int stn = kf & (NSTAGE - 1);
            int k0 = kf * BK;
            uint32_t ab = as_base + stn * AS_BUF;
            uint32_t bb = bs_base + stn * BS_BUF;
            cpa16(ab + (a_row * AS_STRIDE + a_kq) * 4, Ap + (size_t)a_row * K + k0 + a_kq);
            cpa16(ab + ((a_row + 64) * AS_STRIDE + a_kq) * 4, Ap + (size_t)(a_row + 64) * K + k0 + a_kq);
            cpa16(bb + (b_row * BS_STRIDE + b_nc) * 4, B + (size_t)(k0 + b_row) * 512 + bn + b_nc);
            cpa16(bb + ((b_row + 8) * BS_STRIDE + b_nc) * 4, B + (size_t)(k0 + b_row + 8) * 512 + bn + b_nc);
        }
        cp_commit();  // unconditional: keeps 1 group/iter invariant

        const float* As_st = AsBase + st * AS_TILE;
        const float* Bs_st = BsBase + st * BS_TILE;

        #pragma unroll
        for (int s = 0; s < 2; s++) {
            uint32_t a[4][4], b[4][2];
            #pragma unroll
            for (int mi = 0; mi < 4; mi++) {
                int r = wm * 64 + mi * 16;
                a[mi][0] = __float_as_uint(As_st[(r + g) * AS_STRIDE + s * 8 + t4]);
                a[mi][1] = __float_as_uint(As_st[(r + 8 + g) * AS_STRIDE + s * 8 + t4]);
                a[mi][2] = __float_as_uint(As_st[(r + g) * AS_STRIDE + s * 8 + t4 + 4]);
                a[mi][3] = __float_as_uint(As_st[(r + 8 + g) * AS_STRIDE + s * 8 + t4 + 4]);
            }
            #pragma unroll
            for (int nj = 0; nj < 4; nj++) {
                int c = wn * 32 + nj * 8 + g;
                b[nj][0] = __float_as_uint(Bs_st[(s * 8 + t4) * BS_STRIDE + c]);
                b[nj][1] = __float_as_uint(Bs_st[(s * 8 + t4 + 4) * BS_STRIDE + c]);
            }
            #pragma unroll
            for (int mi = 0; mi < 4; mi++)
                #pragma unroll
                for (int nj = 0; nj < 4; nj++)
                    mma_tf32(acc[mi][nj], a[mi], b[nj]);
        }
    }

    #pragma unroll
    for (int mi = 0; mi < 4; mi++) {
        int r0 = bm + wm * 64 + mi * 16 + g;
        int r1 = r0 + 8;
        #pragma unroll
        for (int nj = 0; nj < 4; nj++) {
            int c = bn + wn * 32 + nj * 8 + 2 * t4;
            *(float2*)(C + (size_t)r0 * 512 + c) = make_float2(acc[mi][nj][0], acc[mi][nj][1]);
            *(float2*)(C + (size_t)r1 * 512 + c) = make_float2(acc[mi][nj][2], acc[mi][nj][3]);
        }
    }

    if (o1 || o2) {
        float w1v[4][2], w2v[4][2];
        #pragma unroll
        for (int nj = 0; nj < 4; nj++) {
            int c = wn * 32 + nj * 8 + 2 * t4;
            if (o1) { w1v[nj][0] = v1[h * 128 + c]; w1v[nj][1] = v1[h * 128 + c + 1]; }
            if (o2) { w2v[nj][0] = v2[h * 128 + c]; w2v[nj][1] = v2[h * 128 + c + 1]; }
        }
        #pragma unroll
        for (int mi = 0; mi < 4; mi++) {
            float p0 = 0.f, p1 = 0.f, q0 = 0.f, q1 = 0.f;
            #pragma unroll
            for (int nj = 0; nj < 4; nj++) {
                if (o1) {
                    p0 += acc[mi][nj][0] * w1v[nj][0] + acc[mi][nj][1] * w1v[nj][1];
                    p1 += acc[mi][nj][2] * w1v[nj][0] + acc[mi][nj][3] * w1v[nj][1];
                }
                if (o2) {
                    q0 += acc[mi][nj][0] * w2v[nj][0] + acc[mi][nj][1] * w2v[nj][1];
                    q1 += acc[mi][nj][2] * w2v[nj][0] + acc[mi][nj][3] * w2v[nj][1];
                }
            }
            p0 += __shfl_down_sync(0xffffffffu, p0, 2, 4);
            p0 += __shfl_down_sync(0xffffffffu, p0, 1, 4);
            p1 += __shfl_down_sync(0xffffffffu, p1, 2, 4);
            p1 += __shfl_down_sync(0xffffffffu, p1, 1, 4);
            q0 += __shfl_down_sync(0xffffffffu, q0, 2, 4);
            q0 += __shfl_down_sync(0xffffffffu, q0, 1, 4);
            q1 += __shfl_down_sync(0xffffffffu, q1, 2, 4);
            q1 += __shfl_down_sync(0xffffffffu, q1, 1, 4);
            if (t4 == 0) {
                int lr = wm * 64 + mi * 16 + g;
                if (o1) { atomicAdd(&sdot1[lr], p0); atomicAdd(&sdot1[lr + 8], p1); }
                if (o2) { atomicAdd(&sdot2[lr], q0); atomicAdd(&sdot2[lr + 8], q1); }
            }
        }
        __syncthreads();
        if (tid < BM) {
            if (o1) o1[(bm + tid) * H_N + h] = sdot1[tid];
            if (o2) o2[(bm + tid) * H_N + h] = sdot2[tid];
        }
    }
}

// ---------------------------------------------------------------------------
// Fused aggregation: two-pass softmax + weighted gather + bias + head-sum + relu
// ---------------------------------------------------------------------------
__global__ __launch_bounds__(128) void k_aggregate(
    const int* __restrict__ begp, const int* __restrict__ degp,
    const int* __restrict__ ci,
    const float* __restrict__ z,
    const float* __restrict__ el, const float* __restrict__ er,
    const float* __restrict__ bias,
    float* __restrict__ out, int n, int round_out) {
    int node = blockIdx.x;
    if (node >= n) return;
    int t = threadIdx.x;
    int h = t >> 5, lane = t & 31;
    int col = h * F_OUT + lane * 4;

    int beg = begp[node];
    int end = beg + degp[node];
    float erh = er[node * H_N + h];

    float m = -3.0e38f;
    for (int j = beg; j < end; j++) {
        int s = ci[j];
        float e = el[s * H_N + h] + erh;
        e = (e > 0.f) ? e : 0.2f * e;
        m = fmaxf(m, e);
    }

    float4 acc = make_float4(0.f, 0.f, 0.f, 0.f);
    float ssum = 0.f;
    for (int j = beg; j < end; j++) {
        int s = ci[j];
        float e = el[s * H_N + h] + erh;
        e = (e > 0.f) ? e : 0.2f * e;
        float w = __expf(e - m);
        float4 zv = *(const float4*)(z + (size_t)s * HF + col);
        acc.x += w * zv.x; acc.y += w * zv.y;
        acc.z += w * zv.z; acc.w += w * zv.w;
        ssum += w;
    }

    float4 bv = *(const float4*)(bias + col);
    float4 o;
    if (end > beg) {
        float inv = 1.f / ssum;
        o = make_float4(acc.x * inv + bv.x, acc.y * inv + bv.y,
                        acc.z * inv + bv.z, acc.w * inv + bv.w);
    } else {
        o = bv;
    }

    __shared__ float sm[HF];
    *(float4*)(&sm[col]) = o;
    __syncthreads();
    float r = sm[t] + sm[128 + t] + sm[256 + t] + sm[384 + t];
    r = fmaxf(r, 0.f);
    if (round_out) r = roundtf(r);
    out[(size_t)node * F_OUT + t] = r;
}

// ---------------------------------------------------------------------------
// Host launch
// ---------------------------------------------------------------------------
extern "C" void kernel_launch(void* const* d_in, const int* in_sizes, int n_in,
                              void* d_out, int out_size) {
    const float* x_word = (const float*)d_in[0];
    const float* x_doc  = (const float*)d_in[1];
    const float* W_ww0  = (const float*)d_in[2];
    const float* al_ww0 = (const float*)d_in[3];
    const float* ar_ww0 = (const float*)d_in[4];
    const float* b_ww0  = (const float*)d_in[5];
    const float* W_wd0  = (const float*)d_in[6];
    const float* al_wd0 = (const float*)d_in[7];
    const float* ar_wd0 = (const float*)d_in[8];
    const float* b_wd0  = (const float*)d_in[9];
    const float* W_ww1  = (const float*)d_in[10];
    const float* al_ww1 = (const float*)d_in[11];
    const float* ar_ww1 = (const float*)d_in[12];
    const float* b_ww1  = (const float*)d_in[13];
    const float* W_wd1  = (const float*)d_in[14];
    const float* al_wd1 = (const float*)d_in[15];
    const float* ar_wd1 = (const float*)d_in[16];
    const float* b_wd1  = (const float*)d_in[17];
    const int* ww_src = (const int*)d_in[18];
    const int* ww_dst = (const int*)d_in[19];
    const int* wd_src = (const int*)d_in[20];
    const int* wd_dst = (const int*)d_in[21];

    float* out = (float*)d_out;

    float *z_ww, *z_wd, *zd_wd, *el_ww, *er_ww, *el_wd, *er_wd, *xw1, *xd1;
    float *xw_r, *xd_r, *w0a, *w0b, *w1a, *w1b;
    int *deg_ww, *deg_wd, *beg_ww, *beg_wd, *cur, *ci_ww, *ci_wd, *total;
    cudaGetSymbolAddress((void**)&z_ww, g_z_ww);
    cudaGetSymbolAddress((void**)&z_wd, g_z_wd);
    cudaGetSymbolAddress((void**)&zd_wd, g_zd_wd);
    cudaGetSymbolAddress((void**)&el_ww, g_el_ww);
    cudaGetSymbolAddress((void**)&er_ww, g_er_ww);
    cudaGetSymbolAddress((void**)&el_wd, g_el_wd);
    cudaGetSymbolAddress((void**)&er_wd, g_er_wd);
    cudaGetSymbolAddress((void**)&xw1, g_xw1);
    cudaGetSymbolAddress((void**)&xd1, g_xd1);
    cudaGetSymbolAddress((void**)&xw_r, g_xw_r);
    cudaGetSymbolAddress((void**)&xd_r, g_xd_r);
    cudaGetSymbolAddress((void**)&w0a, g_w0a);
    cudaGetSymbolAddress((void**)&w0b, g_w0b);
    cudaGetSymbolAddress((void**)&w1a, g_w1a);
    cudaGetSymbolAddress((void**)&w1b, g_w1b);
    cudaGetSymbolAddress((void**)&deg_ww, g_deg_ww);
    cudaGetSymbolAddress((void**)&deg_wd, g_deg_wd);
    cudaGetSymbolAddress((void**)&beg_ww, g_beg_ww);
    cudaGetSymbolAddress((void**)&beg_wd, g_beg_wd);
    cudaGetSymbolAddress((void**)&cur, g_cur);
    cudaGetSymbolAddress((void**)&ci_ww, g_ci_ww);
    cudaGetSymbolAddress((void**)&ci_wd, g_ci_wd);
    cudaGetSymbolAddress((void**)&total, g_total);

    cudaFuncSetAttribute(k_gemm_tc, cudaFuncAttributeMaxDynamicSharedMemorySize, DYN_SMEM);

    const int TB = 256;

    // ---- 0,1: round x inputs; 2: round all 4 W mats ----
    {
        int n4w = N_W * 256 / 4;
        k_round<<<(n4w + TB - 1) / TB, TB>>>((const float4*)x_word, (float4*)xw_r, n4w);
        int n4d = N_D * 256 / 4;
        k_round<<<(n4d + TB - 1) / TB, TB>>>((const float4*)x_doc, (float4*)xd_r, n4d);
        int a = 256 * 512 / 4, bsz = 128 * 512 / 4;
        int tot = a + a + bsz + bsz;
        k_round4<<<(tot + TB - 1) / TB, TB>>>(
            (const float4*)W_ww0, (float4*)w0a, a,
            (const float4*)W_wd0, (float4*)w0b, a,
            (const float4*)W_ww1, (float4*)w1a, bsz,
            (const float4*)W_wd1, (float4*)w1b, bsz);
    }

    // ---- 3: big ww0 GEMM (profiled launch index 3) ----
    k_gemm_tc<<<dim3(4, N_W / BM), 256, DYN_SMEM>>>(xw_r, w0a, z_ww, al_ww0, ar_ww0,
                                                    el_ww, er_ww, N_W, 256);
    k_gemm_tc<<<dim3(4, N_W / BM), 256, DYN_SMEM>>>(xw_r, w0b, z_wd, al_wd0, nullptr,
                                                    el_wd, nullptr, N_W, 256);
    k_gemm_tc<<<dim3(4, N_D / BM), 256, DYN_SMEM>>>(xd_r, w0b, zd_wd, nullptr, ar_wd0,
                                                    nullptr, er_wd, N_D, 256);

    // ---- CSR ww ----
    k_zero_int<<<(N_W + TB - 1) / TB, TB>>>(deg_ww, N_W);
    k_zero_int<<<1, 32>>>(total, 2);
    k_hist<<<(E_WW + TB - 1) / TB, TB>>>(ww_dst, E_WW, deg_ww);
    k_offsets<<<(N_W + TB - 1) / TB, TB>>>(deg_ww, beg_ww, total, N_W);
    k_zero_int<<<(N_W + TB - 1) / TB, TB>>>(cur, N_W);
    k_scatter<<<(E_WW + TB - 1) / TB, TB>>>(ww_src, ww_dst, E_WW, beg_ww, cur, ci_ww);
    // ---- CSR wd ----
    k_zero_int<<<(N_D + TB - 1) / TB, TB>>>(deg_wd, N_D);
    k_hist<<<(E_WD + TB - 1) / TB, TB>>>(wd_dst, E_WD, deg_wd);
    k_offsets<<<(N_D + TB - 1) / TB, TB>>>(deg_wd, beg_wd, total + 1, N_D);
    k_zero_int<<<(N_D + TB - 1) / TB, TB>>>(cur, N_D);
    k_scatter<<<(E_WD + TB - 1) / TB, TB>>>(wd_src, wd_dst, E_WD, beg_wd, cur, ci_wd);

    // ---- Layer 0 aggregation (outputs rounded to tf32 for next GEMM) ----
    k_aggregate<<<N_W, 128>>>(beg_ww, deg_ww, ci_ww, z_ww, el_ww, er_ww, b_ww0, xw1, N_W, 1);
    k_aggregate<<<N_D, 128>>>(beg_wd, deg_wd, ci_wd, z_wd, el_wd, er_wd, b_wd0, xd1, N_D, 1);

    // ---- Layer 1 ----
    k_gemm_tc<<<dim3(4, N_W / BM), 256, DYN_SMEM>>>(xw1, w1a, z_ww, al_ww1, ar_ww1,
                                                    el_ww, er_ww, N_W, 128);
    k_gemm_tc<<<dim3(4, N_W / BM), 256, DYN_SMEM>>>(xw1, w1b, z_wd, al_wd1, nullptr,
                                                    el_wd, nullptr, N_W, 128);
    k_gemm_tc<<<dim3(4, N_D / BM), 256, DYN_SMEM>>>(xd1, w1b, zd_wd, nullptr, ar_wd1,
                                                    nullptr, er_wd, N_D, 128);
    k_aggregate<<<N_W, 128>>>(beg_ww, deg_ww, ci_ww, z_ww, el_ww, er_ww, b_ww1, out, N_W, 0);
    k_aggregate<<<N_D, 128>>>(beg_wd, deg_wd, ci_wd, z_wd, el_wd, er_wd, b_wd1,
                              out + (size_t)N_W * F_OUT, N_D, 0);
}

// round 13
// speedup vs baseline: 1.0399x; 1.0320x over previous
#include <cuda_runtime.h>
#include <math.h>
#include <stdint.h>

// Problem constants
#define N_W   80000
#define N_D   16000
#define E_WW  200000
#define E_WD  200000
#define HF    512      // H*F = 4*128
#define F_OUT 128
#define H_N   4

// GEMM tiling
#define BM 128
#define BN 128
#define BK 16
#define NSTAGE 4
#define AS_STRIDE 28    // floats; conflict-free frag reads, rows 16B-multiple
#define BS_STRIDE 136   // floats; >=128 cols + pad -> conflict-free, 16B-multiple
#define AS_TILE (BM * AS_STRIDE)
#define BS_TILE (BK * BS_STRIDE)
#define DYN_SMEM ((NSTAGE * (AS_TILE + BS_TILE)) * 4)   // 92160 bytes

// ---------------------------------------------------------------------------
// Static device scratch (allocation-free rule)
// ---------------------------------------------------------------------------
__device__ float g_z_ww[(size_t)N_W * HF];
__device__ float g_z_wd[(size_t)N_W * HF];
__device__ float g_zd_wd[(size_t)N_D * HF];
__device__ float g_el_ww[N_W * H_N];
__device__ float g_er_ww[N_W * H_N];
__device__ float g_el_wd[N_W * H_N];
__device__ float g_er_wd[N_D * H_N];
__device__ float g_xw1[(size_t)N_W * F_OUT];
__device__ float g_xd1[(size_t)N_D * F_OUT];
__device__ float g_xw_r[(size_t)N_W * 256];
__device__ float g_xd_r[(size_t)N_D * 256];
__device__ float g_w0a[256 * 512];
__device__ float g_w0b[256 * 512];
__device__ float g_w1a[128 * 512];
__device__ float g_w1b[128 * 512];
__device__ int   g_deg_ww[N_W];
__device__ int   g_deg_wd[N_D];
__device__ int   g_beg_ww[N_W];
__device__ int   g_beg_wd[N_D];
__device__ int   g_cur_ww[N_W];
__device__ int   g_cur_wd[N_D];
__device__ int   g_ci_ww[E_WW];
__device__ int   g_ci_wd[E_WD];
__device__ int   g_total[2];

// ---------------------------------------------------------------------------
// helpers
// ---------------------------------------------------------------------------
__device__ __forceinline__ uint32_t f2tf(float x) {
    uint32_t r;
    asm("cvt.rna.tf32.f32 %0, %1;" : "=r"(r) : "f"(x));
    return r;
}
__device__ __forceinline__ float roundtf(float x) {
    return __uint_as_float(f2tf(x));
}
__device__ __forceinline__ void cpa16(uint32_t dst, const float* src) {
    asm volatile("cp.async.cg.shared.global [%0], [%1], 16;" :: "r"(dst), "l"(src));
}
__device__ __forceinline__ void cp_commit() {
    asm volatile("cp.async.commit_group;");
}
__device__ __forceinline__ void mma_tf32(float* d, const uint32_t* a, const uint32_t* b) {
    asm volatile(
        "mma.sync.aligned.m16n8k8.row.col.f32.tf32.tf32.f32 "
        "{%0,%1,%2,%3}, {%4,%5,%6,%7}, {%8,%9}, {%0,%1,%2,%3};\n"
        : "+f"(d[0]), "+f"(d[1]), "+f"(d[2]), "+f"(d[3])
        : "r"(a[0]), "r"(a[1]), "r"(a[2]), "r"(a[3]), "r"(b[0]), "r"(b[1]));
}

// ---------------------------------------------------------------------------
// tf32 pre-rounding kernels
// ---------------------------------------------------------------------------
__global__ void k_round(const float4* __restrict__ src, float4* __restrict__ dst, int n4) {
    int i = blockIdx.x * blockDim.x + threadIdx.x;
    if (i < n4) {
        float4 v = src[i];
        v.x = roundtf(v.x); v.y = roundtf(v.y);
        v.z = roundtf(v.z); v.w = roundtf(v.w);
        dst[i] = v;
    }
}

__global__ void k_round4(const float4* s0, float4* d0, int n0,
                         const float4* s1, float4* d1, int n1,
                         const float4* s2, float4* d2, int n2,
                         const float4* s3, float4* d3, int n3) {
    int i = blockIdx.x * blockDim.x + threadIdx.x;
    const float4* s; float4* d; int j = i;
    if (j < n0) { s = s0; d = d0; }
    else { j -= n0;
        if (j < n1) { s = s1; d = d1; }
        else { j -= n1;
            if (j < n2) { s = s2; d = d2; }
            else { j -= n2;
                if (j < n3) { s = s3; d = d3; }
                else return;
            }
        }
    }
    float4 v = s[j];
    v.x = roundtf(v.x); v.y = roundtf(v.y);
    v.z = roundtf(v.z); v.w = roundtf(v.w);
    d[j] = v;
}

// ---------------------------------------------------------------------------
// Merged CSR build (both relations per launch)
// ---------------------------------------------------------------------------
__global__ void k_zero_multi(int* p0, int n0, int* p1, int n1,
                             int* p2, int n2, int* p3, int n3,
                             int* p4, int n4) {
    int i = blockIdx.x * blockDim.x + threadIdx.x;
    int* p; int j = i;
    if (j < n0) p = p0;
    else { j -= n0;
        if (j < n1) p = p1;
        else { j -= n1;
            if (j < n2) p = p2;
            else { j -= n2;
                if (j < n3) p = p3;
                else { j -= n3;
                    if (j < n4) p = p4;
                    else return;
                }
            }
        }
    }
    p[j] = 0;
}

__global__ void k_hist2(const int* __restrict__ dst_ww, const int* __restrict__ dst_wd,
                        int* __restrict__ deg_ww, int* __restrict__ deg_wd) {
    int i = blockIdx.x * blockDim.x + threadIdx.x;
    if (i < E_WW) atomicAdd(&deg_ww[dst_ww[i]], 1);
    else if (i < E_WW + E_WD) atomicAdd(&deg_wd[dst_wd[i - E_WW]], 1);
}

// N_W and N_D are multiples of 32 -> each warp stays within one segment
__global__ void k_offsets2(const int* __restrict__ deg_ww, int* __restrict__ beg_ww,
                           const int* __restrict__ deg_wd, int* __restrict__ beg_wd,
                           int* __restrict__ total) {
    int i = blockIdx.x * blockDim.x + threadIdx.x;
    int lane = threadIdx.x & 31;
    const int* deg; int* beg; int* tot; int j; bool ok = true;
    if (i < N_W) { deg = deg_ww; beg = beg_ww; tot = total; j = i; }
    else if (i < N_W + N_D) { deg = deg_wd; beg = beg_wd; tot = total + 1; j = i - N_W; }
    else ok = false;
    int v = ok ? deg[j] : 0;
    int s = v;
    #pragma unroll
    for (int off = 1; off < 32; off <<= 1) {
        int t = __shfl_up_sync(0xffffffffu, s, off);
        if (lane >= off) s += t;
    }
    int wtot = __shfl_sync(0xffffffffu, s, 31);
    int base = 0;
    if (lane == 31 && ok) base = atomicAdd(tot, wtot);
    base = __shfl_sync(0xffffffffu, base, 31);
    if (ok) beg[j] = base + s - v;
}

__global__ void k_scatter2(const int* __restrict__ ww_src, const int* __restrict__ ww_dst,
                           const int* __restrict__ wd_src, const int* __restrict__ wd_dst,
                           const int* __restrict__ beg_ww, int* __restrict__ cur_ww,
                           int* __restrict__ ci_ww,
                           const int* __restrict__ beg_wd, int* __restrict__ cur_wd,
                           int* __restrict__ ci_wd) {
    int i = blockIdx.x * blockDim.x + threadIdx.x;
    if (i < E_WW) {
        int d = ww_dst[i];
        int p = atomicAdd(&cur_ww[d], 1);
        ci_ww[beg_ww[d] + p] = ww_src[i];
    } else if (i < E_WW + E_WD) {
        int j = i - E_WW;
        int d = wd_dst[j];
        int p = atomicAdd(&cur_wd[d], 1);
        ci_wd[beg_wd[d] + p] = wd_src[j];
    }
}

// ---------------------------------------------------------------------------
// TF32 tensor-core GEMM (3 segments in one launch): C[M,512] = A[M,K] @ B[K,512]
// Inputs PRE-ROUNDED to tf32. 128x128 tile, 512 threads, 16 warps (4m x 4n),
// warptile 32x32, mma.m16n8k8.tf32, 4-stage cp.async, 1 barrier/iter.
// Fused per-head attention-dot epilogue.
// ---------------------------------------------------------------------------
__global__ __launch_bounds__(512, 2) void k_gemm3(
    const float* __restrict__ A0, const float* __restrict__ B0, float* __restrict__ C0,
    const float* __restrict__ v10, const float* __restrict__ v20,
    float* __restrict__ o10, float* __restrict__ o20, int t0,
    const float* __restrict__ A1, const float* __restrict__ B1, float* __restrict__ C1,
    const float* __restrict__ v11, const float* __restrict__ v21,
    float* __restrict__ o11, float* __restrict__ o21, int t1,
    const float* __restrict__ A2, const float* __restrict__ B2, float* __restrict__ C2,
    const float* __restrict__ v12, const float* __restrict__ v22,
    float* __restrict__ o12, float* __restrict__ o22,
    int K) {
    extern __shared__ __align__(16) float dsm[];
    __shared__ float sdot1[BM];
    __shared__ float sdot2[BM];

    float* AsBase = dsm;
    float* BsBase = dsm + NSTAGE * AS_TILE;

    int by = blockIdx.y;
    const float *A, *Bm, *v1, *v2;
    float *C, *o1, *o2;
    if (by < t0) { A = A0; Bm = B0; C = C0; v1 = v10; v2 = v20; o1 = o10; o2 = o20; }
    else if (by < t0 + t1) { by -= t0; A = A1; Bm = B1; C = C1; v1 = v11; v2 = v21; o1 = o11; o2 = o21; }
    else { by -= t0 + t1; A = A2; Bm = B2; C = C2; v1 = v12; v2 = v22; o1 = o12; o2 = o22; }

    int tid = threadIdx.x;
    int lane = tid & 31, wid = tid >> 5;
    int g = lane >> 2, t4 = lane & 3;
    int wm = wid & 3, wn = wid >> 2;       // 4 x 4 warps, warptile 32x32
    int bm = by * BM;
    int h  = blockIdx.x;
    int bn = h * BN;

    if (tid < BM) { sdot1[tid] = 0.f; sdot2[tid] = 0.f; }

    // staging: one float4 per thread for A (128x16) and B (16x128)
    int a_row = tid >> 2;            // 0..127
    int a_kq  = (tid & 3) * 4;       // 0,4,8,12
    int b_row = tid >> 5;            // 0..15
    int b_nc  = (tid & 31) * 4;      // 0..124

    const float* Ap = A + (size_t)bm * K;

    uint32_t as_base = (uint32_t)__cvta_generic_to_shared(AsBase);
    uint32_t bs_base = (uint32_t)__cvta_generic_to_shared(BsBase);
    const uint32_t AS_BUF = AS_TILE * 4;
    const uint32_t BS_BUF = BS_TILE * 4;

    float acc[2][4][4] = {};

    int nk = K / BK;

    // prologue: stage buffers 0..2
    #pragma unroll
    for (int st = 0; st < NSTAGE - 1; st++) {
        int k0 = st * BK;
        cpa16(as_base + st * AS_BUF + (a_row * AS_STRIDE + a_kq) * 4,
              Ap + (size_t)a_row * K + k0 + a_kq);
        cpa16(bs_base + st * BS_BUF + (b_row * BS_STRIDE + b_nc) * 4,
              Bm + (size_t)(k0 + b_row) * 512 + bn + b_nc);
        cp_commit();
    }

    for (int kt = 0; kt < nk; kt++) {
        int st = kt & (NSTAGE - 1);
        asm volatile("cp.async.wait_group %0;" :: "n"(NSTAGE - 2));
        __syncthreads();

        if (kt + NSTAGE - 1 < nk) {
            int kf = kt + NSTAGE - 1;
            int stn = kf & (NSTAGE - 1);
            int k0 = kf * BK;
            cpa16(as_base + stn * AS_BUF + (a_row * AS_STRIDE + a_kq) * 4,
                  Ap + (size_t)a_row * K + k0 + a_kq);
            cpa16(bs_base + stn * BS_BUF + (b_row * BS_STRIDE + b_nc) * 4,
                  Bm + (size_t)(k0 + b_row) * 512 + bn + b_nc);
        }
        cp_commit();

        const float* As_st = AsBase + st * AS_TILE;
        const float* Bs_st = BsBase + st * BS_TILE;

        #pragma unroll
        for (int s = 0; s < 2; s++) {
            uint32_t a[2][4], b[4][2];
            #pragma unroll
            for (int mi = 0; mi < 2; mi++) {
                int r = wm * 32 + mi * 16;
                a[mi][0] = __float_as_uint(As_st[(r + g) * AS_STRIDE + s * 8 + t4]);
                a[mi][1] = __float_as_uint(As_st[(r + 8 + g) * AS_STRIDE + s * 8 + t4]);
                a[mi][2] = __float_as_uint(As_st[(r + g) * AS_STRIDE + s * 8 + t4 + 4]);
                a[mi][3] = __float_as_uint(As_st[(r + 8 + g) * AS_STRIDE + s * 8 + t4 + 4]);
            }
            #pragma unroll
            for (int nj = 0; nj < 4; nj++) {
                int c = wn * 32 + nj * 8 + g;
                b[nj][0] = __float_as_uint(Bs_st[(s * 8 + t4) * BS_STRIDE + c]);
                b[nj][1] = __float_as_uint(Bs_st[(s * 8 + t4 + 4) * BS_STRIDE + c]);
            }
            #pragma unroll
            for (int mi = 0; mi < 2; mi++)
                #pragma unroll
                for (int nj = 0; nj < 4; nj++)
                    mma_tf32(acc[mi][nj], a[mi], b[nj]);
        }
    }

    #pragma unroll
    for (int mi = 0; mi < 2; mi++) {
        int r0 = bm + wm * 32 + mi * 16 + g;
        int r1 = r0 + 8;
        #pragma unroll
        for (int nj = 0; nj < 4; nj++) {
            int c = bn + wn * 32 + nj * 8 + 2 * t4;
            *(float2*)(C + (size_t)r0 * 512 + c) = make_float2(acc[mi][nj][0], acc[mi][nj][1]);
            *(float2*)(C + (size_t)r1 * 512 + c) = make_float2(acc[mi][nj][2], acc[mi][nj][3]);
        }
    }

    if (o1 || o2) {
        float w1v[4][2], w2v[4][2];
        #pragma unroll
        for (int nj = 0; nj < 4; nj++) {
            int c = wn * 32 + nj * 8 + 2 * t4;
            if (o1) { w1v[nj][0] = v1[h * 128 + c]; w1v[nj][1] = v1[h * 128 + c + 1]; }
            if (o2) { w2v[nj][0] = v2[h * 128 + c]; w2v[nj][1] = v2[h * 128 + c + 1]; }
        }
        #pragma unroll
        for (int mi = 0; mi < 2; mi++) {
            float p0 = 0.f, p1 = 0.f, q0 = 0.f, q1 = 0.f;
            #pragma unroll
            for (int nj = 0; nj < 4; nj++) {
                if (o1) {
                    p0 += acc[mi][nj][0] * w1v[nj][0] + acc[mi][nj][1] * w1v[nj][1];
                    p1 += acc[mi][nj][2] * w1v[nj][0] + acc[mi][nj][3] * w1v[nj][1];
                }
                if (o2) {
                    q0 += acc[mi][nj][0] * w2v[nj][0] + acc[mi][nj][1] * w2v[nj][1];
                    q1 += acc[mi][nj][2] * w2v[nj][0] + acc[mi][nj][3] * w2v[nj][1];
                }
            }
            p0 += __shfl_down_sync(0xffffffffu, p0, 2, 4);
            p0 += __shfl_down_sync(0xffffffffu, p0, 1, 4);
            p1 += __shfl_down_sync(0xffffffffu, p1, 2, 4);
            p1 += __shfl_down_sync(0xffffffffu, p1, 1, 4);
            q0 += __shfl_down_sync(0xffffffffu, q0, 2, 4);
            q0 += __shfl_down_sync(0xffffffffu, q0, 1, 4);
            q1 += __shfl_down_sync(0xffffffffu, q1, 2, 4);
            q1 += __shfl_down_sync(0xffffffffu, q1, 1, 4);
            if (t4 == 0) {
                int lr = wm * 32 + mi * 16 + g;
                if (o1) { atomicAdd(&sdot1[lr], p0); atomicAdd(&sdot1[lr + 8], p1); }
                if (o2) { atomicAdd(&sdot2[lr], q0); atomicAdd(&sdot2[lr + 8], q1); }
            }
        }
        __syncthreads();
        if (tid < BM) {
            if (o1) o1[(bm + tid) * H_N + h] = sdot1[tid];
            if (o2) o2[(bm + tid) * H_N + h] = sdot2[tid];
        }
    }
}

// ---------------------------------------------------------------------------
// Merged aggregation (both relations in one launch): two-pass softmax +
// weighted gather + bias + head-sum + relu. 128 threads = 4 heads.
// ---------------------------------------------------------------------------
__global__ __launch_bounds__(128) void k_agg2(
    const int* __restrict__ beg_ww, const int* __restrict__ deg_ww,
    const int* __restrict__ ci_ww,
    const float* __restrict__ z_ww, const float* __restrict__ el_ww,
    const float* __restrict__ er_ww, const float* __restrict__ b_ww,
    float* __restrict__ out_ww,
    const int* __restrict__ beg_wd, const int* __restrict__ deg_wd,
    const int* __restrict__ ci_wd,
    const float* __restrict__ z_wd, const float* __restrict__ el_wd,
    const float* __restrict__ er_wd, const float* __restrict__ b_wd,
    float* __restrict__ out_wd,
    int round_out) {
    int nb = blockIdx.x;
    const int *begp, *degp, *ci;
    const float *z, *el, *er, *bias;
    float* out;
    int node;
    if (nb < N_W) {
        node = nb;
        begp = beg_ww; degp = deg_ww; ci = ci_ww;
        z = z_ww; el = el_ww; er = er_ww; bias = b_ww; out = out_ww;
    } else {
        node = nb - N_W;
        begp = beg_wd; degp = deg_wd; ci = ci_wd;
        z = z_wd; el = el_wd; er = er_wd; bias = b_wd; out = out_wd;
    }

    int t = threadIdx.x;
    int h = t >> 5, lane = t & 31;
    int col = h * F_OUT + lane * 4;

    int beg = begp[node];
    int end = beg + degp[node];
    float erh = er[node * H_N + h];

    float m = -3.0e38f;
    for (int j = beg; j < end; j++) {
        int s = ci[j];
        float e = el[s * H_N + h] + erh;
        e = (e > 0.f) ? e : 0.2f * e;
        m = fmaxf(m, e);
    }

    float4 acc = make_float4(0.f, 0.f, 0.f, 0.f);
    float ssum = 0.f;
    for (int j = beg; j < end; j++) {
        int s = ci[j];
        float e = el[s * H_N + h] + erh;
        e = (e > 0.f) ? e : 0.2f * e;
        float w = __expf(e - m);
        float4 zv = *(const float4*)(z + (size_t)s * HF + col);
        acc.x += w * zv.x; acc.y += w * zv.y;
        acc.z += w * zv.z; acc.w += w * zv.w;
        ssum += w;
    }

    float4 bv = *(const float4*)(bias + col);
    float4 o;
    if (end > beg) {
        float inv = 1.f / ssum;
        o = make_float4(acc.x * inv + bv.x, acc.y * inv + bv.y,
                        acc.z * inv + bv.z, acc.w * inv + bv.w);
    } else {
        o = bv;
    }

    __shared__ float sm[HF];
    *(float4*)(&sm[col]) = o;
    __syncthreads();
    float r = sm[t] + sm[128 + t] + sm[256 + t] + sm[384 + t];
    r = fmaxf(r, 0.f);
    if (round_out) r = roundtf(r);
    out[(size_t)node * F_OUT + t] = r;
}

// ---------------------------------------------------------------------------
// Host launch
// ---------------------------------------------------------------------------
extern "C" void kernel_launch(void* const* d_in, const int* in_sizes, int n_in,
                              void* d_out, int out_size) {
    const float* x_word = (const float*)d_in[0];
    const float* x_doc  = (const float*)d_in[1];
    const float* W_ww0  = (const float*)d_in[2];
    const float* al_ww0 = (const float*)d_in[3];
    const float* ar_ww0 = (const float*)d_in[4];
    const float* b_ww0  = (const float*)d_in[5];
    const float* W_wd0  = (const float*)d_in[6];
    const float* al_wd0 = (const float*)d_in[7];
    const float* ar_wd0 = (const float*)d_in[8];
    const float* b_wd0  = (const float*)d_in[9];
    const float* W_ww1  = (const float*)d_in[10];
    const float* al_ww1 = (const float*)d_in[11];
    const float* ar_ww1 = (const float*)d_in[12];
    const float* b_ww1  = (const float*)d_in[13];
    const float* W_wd1  = (const float*)d_in[14];
    const float* al_wd1 = (const float*)d_in[15];
    const float* ar_wd1 = (const float*)d_in[16];
    const float* b_wd1  = (const float*)d_in[17];
    const int* ww_src = (const int*)d_in[18];
    const int* ww_dst = (const int*)d_in[19];
    const int* wd_src = (const int*)d_in[20];
    const int* wd_dst = (const int*)d_in[21];

    float* out = (float*)d_out;

    float *z_ww, *z_wd, *zd_wd, *el_ww, *er_ww, *el_wd, *er_wd, *xw1, *xd1;
    float *xw_r, *xd_r, *w0a, *w0b, *w1a, *w1b;
    int *deg_ww, *deg_wd, *beg_ww, *beg_wd, *cur_ww, *cur_wd, *ci_ww, *ci_wd, *total;
    cudaGetSymbolAddress((void**)&z_ww, g_z_ww);
    cudaGetSymbolAddress((void**)&z_wd, g_z_wd);
    cudaGetSymbolAddress((void**)&zd_wd, g_zd_wd);
    cudaGetSymbolAddress((void**)&el_ww, g_el_ww);
    cudaGetSymbolAddress((void**)&er_ww, g_er_ww);
    cudaGetSymbolAddress((void**)&el_wd, g_el_wd);
    cudaGetSymbolAddress((void**)&er_wd, g_er_wd);
    cudaGetSymbolAddress((void**)&xw1, g_xw1);
    cudaGetSymbolAddress((void**)&xd1, g_xd1);
    cudaGetSymbolAddress((void**)&xw_r, g_xw_r);
    cudaGetSymbolAddress((void**)&xd_r, g_xd_r);
    cudaGetSymbolAddress((void**)&w0a, g_w0a);
    cudaGetSymbolAddress((void**)&w0b, g_w0b);
    cudaGetSymbolAddress((void**)&w1a, g_w1a);
    cudaGetSymbolAddress((void**)&w1b, g_w1b);
    cudaGetSymbolAddress((void**)&deg_ww, g_deg_ww);
    cudaGetSymbolAddress((void**)&deg_wd, g_deg_wd);
    cudaGetSymbolAddress((void**)&beg_ww, g_beg_ww);
    cudaGetSymbolAddress((void**)&beg_wd, g_beg_wd);
    cudaGetSymbolAddress((void**)&cur_ww, g_cur_ww);
    cudaGetSymbolAddress((void**)&cur_wd, g_cur_wd);
    cudaGetSymbolAddress((void**)&ci_ww, g_ci_ww);
    cudaGetSymbolAddress((void**)&ci_wd, g_ci_wd);
    cudaGetSymbolAddress((void**)&total, g_total);

    cudaFuncSetAttribute(k_gemm3, cudaFuncAttributeMaxDynamicSharedMemorySize, DYN_SMEM);

    const int TB = 256;
    const int TW = N_W / BM;   // 625
    const int TD = N_D / BM;   // 125

    // ---- 0,1: round x inputs; 2: round all 4 W mats ----
    {
        int n4w = N_W * 256 / 4;
        k_round<<<(n4w + TB - 1) / TB, TB>>>((const float4*)x_word, (float4*)xw_r, n4w);
        int n4d = N_D * 256 / 4;
        k_round<<<(n4d + TB - 1) / TB, TB>>>((const float4*)x_doc, (float4*)xd_r, n4d);
        int a = 256 * 512 / 4, bsz = 128 * 512 / 4;
        int tot = a + a + bsz + bsz;
        k_round4<<<(tot + TB - 1) / TB, TB>>>(
            (const float4*)W_ww0, (float4*)w0a, a,
            (const float4*)W_wd0, (float4*)w0b, a,
            (const float4*)W_ww1, (float4*)w1a, bsz,
            (const float4*)W_wd1, (float4*)w1b, bsz);
    }

    // ---- 3: merged L0 GEMMs (profiled launch index 3) ----
    k_gemm3<<<dim3(4, TW + TW + TD), 512, DYN_SMEM>>>(
        xw_r, w0a, z_ww, al_ww0, ar_ww0, el_ww, er_ww, TW,
        xw_r, w0b, z_wd, al_wd0, nullptr, el_wd, nullptr, TW,
        xd_r, w0b, zd_wd, nullptr, ar_wd0, nullptr, er_wd,
        256);

    // ---- merged CSR ----
    k_zero_multi<<<(N_W + N_D + N_W + N_D + 2 + TB - 1) / TB, TB>>>(
        deg_ww, N_W, deg_wd, N_D, cur_ww, N_W, cur_wd, N_D, total, 2);
    k_hist2<<<(E_WW + E_WD + TB - 1) / TB, TB>>>(ww_dst, wd_dst, deg_ww, deg_wd);
    k_offsets2<<<(N_W + N_D + TB - 1) / TB, TB>>>(deg_ww, beg_ww, deg_wd, beg_wd, total);
    k_scatter2<<<(E_WW + E_WD + TB - 1) / TB, TB>>>(
        ww_src, ww_dst, wd_src, wd_dst,
        beg_ww, cur_ww, ci_ww, beg_wd, cur_wd, ci_wd);

    // ---- merged L0 aggregation (outputs tf32-rounded) ----
    k_agg2<<<N_W + N_D, 128>>>(
        beg_ww, deg_ww, ci_ww, z_ww, el_ww, er_ww, b_ww0, xw1,
        beg_wd, deg_wd, ci_wd, z_wd, el_wd, er_wd, b_wd0, xd1, 1);

    // ---- merged L1 GEMMs ----
    k_gemm3<<<dim3(4, TW + TW + TD), 512, DYN_SMEM>>>(
        xw1, w1a, z_ww, al_ww1, ar_ww1, el_ww, er_ww, TW,
        xw1, w1b, z_wd, al_wd1, nullptr, el_wd, nullptr, TW,
        xd1, w1b, zd_wd, nullptr, ar_wd1, nullptr, er_wd,
        128);

    // ---- merged L1 aggregation -> output ----
    k_agg2<<<N_W + N_D, 128>>>(
        beg_ww, deg_ww, ci_ww, z_ww, el_ww, er_ww, b_ww1, out,
        beg_wd, deg_wd, ci_wd, z_wd, el_wd, er_wd, b_wd1,
        out + (size_t)N_W * F_OUT, 0);
}